// round 15
// baseline (speedup 1.0000x reference)
#include <cuda_runtime.h>
#include <cuda_bf16.h>
#include <cstdint>

// Problem constants
#define BB   32
#define SS   64
#define DD   512
#define MM   8192
#define NHD  8
#define HD   64
#define NTOK (BB * SS)          // 2048
#define KSPLIT 4

typedef unsigned short u16;
typedef unsigned int   u32;

// ---------------------------------------------------------------------------
// Scratch (device globals per allocation rules)
// ---------------------------------------------------------------------------
__device__ float g_Q[NTOK * DD];           // Q projection output (fp32)
__device__ float g_KV[MM * 2 * DD];        // K|V projection output (fp32)
// Pre-split bf16 inputs/weights (hi/lo)
__device__ u16 g_qih[NTOK * DD],  g_qil[NTOK * DD];      // query input
__device__ u16 g_bkh[MM * DD],    g_bkl[MM * DD];        // memory_bank
__device__ u16 g_wih[3 * DD * DD], g_wil[3 * DD * DD];   // in_proj_w
__device__ u16 g_woh[DD * DD],    g_wol[DD * DD];        // out_proj_w
__device__ u16 g_aoh[NTOK * DD],  g_aol[NTOK * DD];      // attention output
// Attention operand layouts: K row-major [h][m][d], V transposed [h][d][m]
__device__ u16 g_Kh[NHD * MM * HD], g_Kl[NHD * MM * HD];
__device__ u16 g_Vth[NHD * HD * MM], g_Vtl[NHD * HD * MM];
// Split-K attention partials (unnormalized)
__device__ float g_Opart[KSPLIT][NTOK * DD];
__device__ float g_Lpart[KSPLIT][NTOK * NHD];

// ---------------------------------------------------------------------------
// Helpers
// ---------------------------------------------------------------------------
__device__ __forceinline__ u32 smem_u32(const void* p) {
    u32 a;
    asm("{ .reg .u64 t; cvta.to.shared.u64 t, %1; cvt.u32.u64 %0, t; }"
        : "=r"(a) : "l"(p));
    return a;
}
// Pack two fp32 into bf16x2 (lo half = a) and the bf16x2 of the residuals.
__device__ __forceinline__ void split2(float a, float b, u32& hi, u32& lo) {
    asm("cvt.rn.bf16x2.f32 %0, %1, %2;" : "=r"(hi) : "f"(b), "f"(a));
    float ra = a - __uint_as_float(hi << 16);
    float rb = b - __uint_as_float(hi & 0xffff0000u);
    asm("cvt.rn.bf16x2.f32 %0, %1, %2;" : "=r"(lo) : "f"(rb), "f"(ra));
}
__device__ __forceinline__ void split1(float x, u16& h, u16& l) {
    __nv_bfloat16 bh = __float2bfloat16(x);
    float r = x - __bfloat162float(bh);
    __nv_bfloat16 bl = __float2bfloat16(r);
    h = *(u16*)&bh;  l = *(u16*)&bl;
}
// m16n8k16 bf16 MMA, fp32 accumulate in place (not volatile -> schedulable).
__device__ __forceinline__ void mma16816(float* c, const u32* a, u32 b0, u32 b1) {
    asm("mma.sync.aligned.m16n8k16.row.col.f32.bf16.bf16.f32 "
        "{%0,%1,%2,%3}, {%4,%5,%6,%7}, {%8,%9}, {%0,%1,%2,%3};"
        : "+f"(c[0]), "+f"(c[1]), "+f"(c[2]), "+f"(c[3])
        : "r"(a[0]), "r"(a[1]), "r"(a[2]), "r"(a[3]), "r"(b0), "r"(b1));
}
// ldmatrix x4: four 8x8 b16 matrices, one per output register.
__device__ __forceinline__ void ldm4(u32& r0, u32& r1, u32& r2, u32& r3, u32 addr) {
    asm("ldmatrix.sync.aligned.m8n8.x4.shared.b16 {%0,%1,%2,%3}, [%4];"
        : "=r"(r0), "=r"(r1), "=r"(r2), "=r"(r3) : "r"(addr));
}

// ---------------------------------------------------------------------------
// Pre-split fp32 -> bf16 hi/lo. n multiple of 512; grid n/512, 256 threads.
// ---------------------------------------------------------------------------
__global__ __launch_bounds__(256) void split_f32(
    const float* __restrict__ src, u16* __restrict__ hi, u16* __restrict__ lo)
{
    int i = blockIdx.x * 256 + threadIdx.x;
    float2 v = *(const float2*)&src[2 * i];
    u32 h, l; split2(v.x, v.y, h, l);
    *(u32*)&hi[2 * i] = h;
    *(u32*)&lo[2 * i] = l;
}

// ---------------------------------------------------------------------------
// Tensor-core projection GEMM on pre-split operands:
//   C[MxN] = A[MxK]*W[NxK]^T + bias[N]   (3-pass bf16, fp32 accumulate)
// Grid (N/64, M/128), 256 threads = 8 warps. ldmatrix.x4 fragment loads.
// Dyn smem (u16): Ah[128][72] @0, Al @9216, Wh[64][72] @18432, Wl @23040.
// ---------------------------------------------------------------------------
#define GPROJ_SMEM 55296

__global__ __launch_bounds__(256) void gemm_mma(
    const u16* __restrict__ Ah_g, const u16* __restrict__ Al_g,
    const u16* __restrict__ Wh_g, const u16* __restrict__ Wl_g,
    const float* __restrict__ bias, float* __restrict__ C,
    int K, int N)
{
    extern __shared__ u16 sm2[];
    const int tid = threadIdx.x, w = tid >> 5, lane = tid & 31;
    const int gid = lane >> 2, t4 = lane & 3;
    const int r8 = lane & 7, sel = lane >> 3;
    const int bm = blockIdx.y * 128, bn = blockIdx.x * 64;

    const u32 smb = smem_u32(sm2);
    // A fragments: m0 rows+0 k+0 | m1 rows+8 k+0 | m2 rows+0 k+8 | m3 rows+8 k+8
    const u32 ab  = smb + (u32)(16 * w + r8 + (sel & 1) * 8) * 144 + (u32)(sel >> 1) * 16;
    const u32 abl = ab + 18432;
    // W fragments combined hi/lo: m0/m1 = Wh b0/b1, m2/m3 = Wl b0/b1
    const u32 wb  = smb + 36864 + (u32)(sel >> 1) * 9216 + (u32)r8 * 144 + (u32)(sel & 1) * 16;

    float acc[8][4];
    #pragma unroll
    for (int j = 0; j < 8; j++)
        #pragma unroll
        for (int i = 0; i < 4; i++) acc[j][i] = 0.f;

    for (int k0 = 0; k0 < K; k0 += 64) {
        __syncthreads();
        // Fill A: 128 rows x 64 u16 per array = 1024 uint4 each
        #pragma unroll
        for (int i = 0; i < 4; i++) {
            int idx = i * 256 + tid;
            int r = idx >> 3, c = (idx & 7) * 8;
            size_t go = (size_t)(bm + r) * K + k0 + c;
            *(uint4*)&sm2[r * 72 + c]        = *(const uint4*)&Ah_g[go];
            *(uint4*)&sm2[9216 + r * 72 + c] = *(const uint4*)&Al_g[go];
        }
        // Fill W: 64 rows -> 512 uint4 each
        #pragma unroll
        for (int i = 0; i < 2; i++) {
            int idx = i * 256 + tid;
            int r = idx >> 3, c = (idx & 7) * 8;
            size_t go = (size_t)(bn + r) * K + k0 + c;
            *(uint4*)&sm2[18432 + r * 72 + c] = *(const uint4*)&Wh_g[go];
            *(uint4*)&sm2[23040 + r * 72 + c] = *(const uint4*)&Wl_g[go];
        }
        __syncthreads();

        #pragma unroll
        for (int kk = 0; kk < 4; kk++) {
            u32 ah[4], al[4];
            ldm4(ah[0], ah[1], ah[2], ah[3], ab  + kk * 32);
            ldm4(al[0], al[1], al[2], al[3], abl + kk * 32);
            #pragma unroll
            for (int j = 0; j < 8; j++) {
                u32 b0, b1, b2, b3;
                ldm4(b0, b1, b2, b3, wb + j * 1152 + kk * 32);
                mma16816(acc[j], ah, b0, b1);
                mma16816(acc[j], al, b0, b1);
                mma16816(acc[j], ah, b2, b3);
            }
        }
    }

    #pragma unroll
    for (int j = 0; j < 8; j++) {
        int row = bm + 16 * w + gid;
        int col = bn + 8 * j + 2 * t4;
        float2 b2 = *(const float2*)&bias[col];
        *(float2*)&C[(size_t)row * N + col] =
            make_float2(acc[j][0] + b2.x, acc[j][1] + b2.y);
        *(float2*)&C[(size_t)(row + 8) * N + col] =
            make_float2(acc[j][2] + b2.x, acc[j][3] + b2.y);
    }
}

// ---------------------------------------------------------------------------
// Split K (row-major bf16 hi/lo) and V (transposed bf16 hi/lo).
// Grid (NHD, MM/64), 256 threads. V staged through smem for coalesced writes.
// ---------------------------------------------------------------------------
__global__ __launch_bounds__(256) void kv_split()
{
    __shared__ float vt[64][65];
    const int h = blockIdx.x, t = blockIdx.y;
    const int m0 = t * 64;
    const int tid = threadIdx.x;

    #pragma unroll
    for (int i = 0; i < 16; i++) {
        int idx = i * 256 + tid;
        int r = idx >> 6, d = idx & 63;
        size_t row = (size_t)(m0 + r) * (2 * DD);
        float kf = g_KV[row + h * HD + d];
        u16 kh, kl; split1(kf, kh, kl);
        size_t ko = ((size_t)h * MM + m0 + r) * HD + d;
        g_Kh[ko] = kh;  g_Kl[ko] = kl;
        vt[r][d] = g_KV[row + DD + h * HD + d];
    }
    __syncthreads();
    #pragma unroll
    for (int i = 0; i < 16; i++) {
        int idx = i * 256 + tid;
        int d = idx >> 6, r = idx & 63;
        u16 vh, vl; split1(vt[r][d], vh, vl);
        size_t vo = ((size_t)h * HD + d) * MM + m0 + r;
        g_Vth[vo] = vh;  g_Vtl[vo] = vl;
    }
}

// ---------------------------------------------------------------------------
// mma.sync flash attention, split-K, shift-free softmax, ldmatrix fragments.
// Grid (NHD, 16 q-blocks, KSPLIT), 256 threads = 8 warps.
// Ks/Vs2 layout [hi|lo][64][72]; one ldmatrix.x4 fetches hi-b0,hi-b1,lo-b0,lo-b1.
// ---------------------------------------------------------------------------
__global__ __launch_bounds__(256, 2) void attn_mma()
{
    __shared__ u16 Ks[2][64][72];
    __shared__ u16 Vs2[2][64][72];

    const int tid = threadIdx.x, w = tid >> 5, lane = tid & 31;
    const int h = blockIdx.x, bp = blockIdx.y, z = blockIdx.z;
    const int gid = lane >> 2, t4 = lane & 3;
    const int r8 = lane & 7, sel = lane >> 3;
    const int q0 = bp * 128 + w * 16;

    // Per-thread ldmatrix base addresses (combined hi/lo)
    const u32 kb = smem_u32(&Ks[sel >> 1][r8][(sel & 1) * 8]);
    const u32 vb = smem_u32(&Vs2[sel >> 1][r8][(sel & 1) * 8]);

    // --- Q fragments (fp32 load, scale 1/8, split to hi/lo bf16x2) ---
    u32 qh[4][4], ql[4][4];
    #pragma unroll
    for (int kk = 0; kk < 4; kk++) {
        const float* qb = &g_Q[(size_t)(q0 + gid) * DD + h * HD + 16 * kk + 2 * t4];
        float2 v;
        v = *(const float2*)(qb);
        split2(v.x * 0.125f, v.y * 0.125f, qh[kk][0], ql[kk][0]);
        v = *(const float2*)(qb + 8 * DD);
        split2(v.x * 0.125f, v.y * 0.125f, qh[kk][1], ql[kk][1]);
        v = *(const float2*)(qb + 8);
        split2(v.x * 0.125f, v.y * 0.125f, qh[kk][2], ql[kk][2]);
        v = *(const float2*)(qb + 8 * DD + 8);
        split2(v.x * 0.125f, v.y * 0.125f, qh[kk][3], ql[kk][3]);
    }

    float oacc[8][4];
    #pragma unroll
    for (int j = 0; j < 8; j++)
        #pragma unroll
        for (int i = 0; i < 4; i++) oacc[j][i] = 0.f;
    float ls0 = 0.f, ls1 = 0.f;

    const size_t kbase = ((size_t)h * MM) * HD;
    const size_t vbase = ((size_t)h * HD) * MM;
    const int t0 = z * (MM / 64 / KSPLIT);

    for (int t = t0; t < t0 + MM / 64 / KSPLIT; t++) {
        __syncthreads();
        // --- cooperative tile copy: 4 arrays x 512 uint4 ---
        {
            const uint4* srcKh = (const uint4*)(g_Kh + kbase + (size_t)t * 64 * HD);
            const uint4* srcKl = (const uint4*)(g_Kl + kbase + (size_t)t * 64 * HD);
            #pragma unroll
            for (int i = 0; i < 2; i++) {
                int idx = i * 256 + tid;
                int r = idx >> 3, c = idx & 7;
                *(uint4*)&Ks[0][r][c * 8] = srcKh[idx];
                *(uint4*)&Ks[1][r][c * 8] = srcKl[idx];
                const uint4* svh = (const uint4*)(g_Vth + vbase + (size_t)r * MM + t * 64);
                const uint4* svl = (const uint4*)(g_Vtl + vbase + (size_t)r * MM + t * 64);
                *(uint4*)&Vs2[0][r][c * 8] = svh[c];
                *(uint4*)&Vs2[1][r][c * 8] = svl[c];
            }
        }
        __syncthreads();

        // --- S = Q K^T ---
        float sacc[8][4];
        #pragma unroll
        for (int j = 0; j < 8; j++)
            #pragma unroll
            for (int i = 0; i < 4; i++) sacc[j][i] = 0.f;

        #pragma unroll
        for (int kk = 0; kk < 4; kk++) {
            #pragma unroll
            for (int j = 0; j < 8; j++) {
                u32 b0, b1, b2, b3;
                ldm4(b0, b1, b2, b3, kb + j * 1152 + kk * 32);
                mma16816(sacc[j], qh[kk], b0, b1);
                mma16816(sacc[j], ql[kk], b0, b1);
                mma16816(sacc[j], qh[kk], b2, b3);
            }
        }

        // --- exp, row-sum, P fragments (hi/lo) ---
        u32 ph[4][4], pl[4][4];
        #pragma unroll
        for (int j = 0; j < 8; j++) {
            float e0 = __expf(sacc[j][0]);
            float e1 = __expf(sacc[j][1]);
            float e2 = __expf(sacc[j][2]);
            float e3 = __expf(sacc[j][3]);
            ls0 += e0 + e1;
            ls1 += e2 + e3;
            int kk = j >> 1, sl = (j & 1) * 2;
            split2(e0, e1, ph[kk][sl + 0], pl[kk][sl + 0]);
            split2(e2, e3, ph[kk][sl + 1], pl[kk][sl + 1]);
        }

        // --- O += P V ---
        #pragma unroll
        for (int kk = 0; kk < 4; kk++) {
            #pragma unroll
            for (int j = 0; j < 8; j++) {
                u32 b0, b1, b2, b3;
                ldm4(b0, b1, b2, b3, vb + j * 1152 + kk * 32);
                mma16816(oacc[j], ph[kk], b0, b1);
                mma16816(oacc[j], pl[kk], b0, b1);
                mma16816(oacc[j], ph[kk], b2, b3);
            }
        }
    }

    // --- finalize: quad-reduce row sums, write unnormalized partials ---
    ls0 += __shfl_xor_sync(0xffffffffu, ls0, 1);
    ls0 += __shfl_xor_sync(0xffffffffu, ls0, 2);
    ls1 += __shfl_xor_sync(0xffffffffu, ls1, 1);
    ls1 += __shfl_xor_sync(0xffffffffu, ls1, 2);
    if (t4 == 0) {
        g_Lpart[z][(q0 + gid) * NHD + h]     = ls0;
        g_Lpart[z][(q0 + gid + 8) * NHD + h] = ls1;
    }
    #pragma unroll
    for (int j = 0; j < 8; j++) {
        float* d0 = &g_Opart[z][(size_t)(q0 + gid) * DD + h * HD + 8 * j + 2 * t4];
        *(float2*)d0 = make_float2(oacc[j][0], oacc[j][1]);
        float* d1 = d0 + 8 * DD;
        *(float2*)d1 = make_float2(oacc[j][2], oacc[j][3]);
    }
}

// ---------------------------------------------------------------------------
// Split-K reduce: AO = (sum_z Opart) / (sum_z Lpart), written pre-split bf16.
// Grid NTOK, 256 threads (2 adjacent elements each).
// ---------------------------------------------------------------------------
__global__ __launch_bounds__(256) void attn_reduce()
{
    const int q = blockIdx.x;
    const int d0 = threadIdx.x * 2;
    const int h = d0 >> 6;
    float l = 0.f, o0 = 0.f, o1 = 0.f;
    #pragma unroll
    for (int s = 0; s < KSPLIT; s++) {
        l += g_Lpart[s][q * NHD + h];
        float2 v = *(const float2*)&g_Opart[s][(size_t)q * DD + d0];
        o0 += v.x;  o1 += v.y;
    }
    float inv = 1.f / l;
    u32 hh, ll;
    split2(o0 * inv, o1 * inv, hh, ll);
    *(u32*)&g_aoh[(size_t)q * DD + d0] = hh;
    *(u32*)&g_aol[(size_t)q * DD + d0] = ll;
}

// ---------------------------------------------------------------------------
// Bank update
// ---------------------------------------------------------------------------
__global__ __launch_bounds__(128) void bank_update(
    const float* __restrict__ memory, const float* __restrict__ bank,
    const int* __restrict__ ptrp, float* __restrict__ outbank)
{
    int r = blockIdx.x;
    int ptr = ptrp[0];
    int rel = (r - ptr) % MM;
    if (rel < 0) rel += MM;
    const float* src = (rel < NTOK) ? (memory + (size_t)rel * DD)
                                    : (bank + (size_t)r * DD);
    float4 v = *(const float4*)(src + threadIdx.x * 4);
    *(float4*)(outbank + (size_t)r * DD + threadIdx.x * 4) = v;
}

// ---------------------------------------------------------------------------
// Launch
// ---------------------------------------------------------------------------
extern "C" void kernel_launch(void* const* d_in, const int* in_sizes, int n_in,
                              void* d_out, int out_size)
{
    const float* query  = (const float*)d_in[0];
    const float* memory = (const float*)d_in[1];
    const float* bank   = (const float*)d_in[2];
    const float* ipw    = (const float*)d_in[3];
    const float* ipb    = (const float*)d_in[4];
    const float* opw    = (const float*)d_in[5];
    const float* opb    = (const float*)d_in[6];
    const int*   ptr    = (const int*)d_in[7];
    float* out = (float*)d_out;

    float *pQ, *pKV;
    cudaGetSymbolAddress((void**)&pQ, g_Q);
    cudaGetSymbolAddress((void**)&pKV, g_KV);
    u16 *pqih, *pqil, *pbkh, *pbkl, *pwih, *pwil, *pwoh, *pwol, *paoh, *paol;
    cudaGetSymbolAddress((void**)&pqih, g_qih);
    cudaGetSymbolAddress((void**)&pqil, g_qil);
    cudaGetSymbolAddress((void**)&pbkh, g_bkh);
    cudaGetSymbolAddress((void**)&pbkl, g_bkl);
    cudaGetSymbolAddress((void**)&pwih, g_wih);
    cudaGetSymbolAddress((void**)&pwil, g_wil);
    cudaGetSymbolAddress((void**)&pwoh, g_woh);
    cudaGetSymbolAddress((void**)&pwol, g_wol);
    cudaGetSymbolAddress((void**)&paoh, g_aoh);
    cudaGetSymbolAddress((void**)&paol, g_aol);

    cudaFuncSetAttribute(gemm_mma, cudaFuncAttributeMaxDynamicSharedMemorySize,
                         GPROJ_SMEM);

    // 0) pre-split inputs and weights to bf16 hi/lo
    split_f32<<<NTOK * DD / 512, 256>>>(query, pqih, pqil);
    split_f32<<<MM * DD / 512, 256>>>(bank, pbkh, pbkl);
    split_f32<<<3 * DD * DD / 512, 256>>>(ipw, pwih, pwil);
    split_f32<<<DD * DD / 512, 256>>>(opw, pwoh, pwol);

    // 1) Q = query @ Wq^T + bq            [2048 x 512]
    gemm_mma<<<dim3(DD / 64, NTOK / 128), 256, GPROJ_SMEM>>>(
        pqih, pqil, pwih, pwil, ipb, pQ, DD, DD);
    // 2) K|V = bank @ [Wk;Wv]^T + [bk;bv] [8192 x 1024]
    gemm_mma<<<dim3(2 * DD / 64, MM / 128), 256, GPROJ_SMEM>>>(
        pbkh, pbkl, pwih + (size_t)DD * DD, pwil + (size_t)DD * DD,
        ipb + DD, pKV, DD, 2 * DD);
    // 3) split K / transpose+split V to attention layouts
    kv_split<<<dim3(NHD, MM / 64), 256>>>();
    // 4) split-K mma.sync flash attention -> partials
    attn_mma<<<dim3(NHD, 16, KSPLIT), 256>>>();
    // 5) combine partials -> pre-split AO
    attn_reduce<<<NTOK, 256>>>();
    // 6) retrieved = AO @ out_proj^T + b
    gemm_mma<<<dim3(DD / 64, NTOK / 128), 256, GPROJ_SMEM>>>(
        paoh, paol, pwoh, pwol, opb, out, DD, DD);
    // 7) new bank
    bank_update<<<MM, 128>>>(memory, bank, ptr, out + (size_t)NTOK * DD);
}

// round 16
// speedup vs baseline: 1.5514x; 1.5514x over previous
#include <cuda_runtime.h>
#include <cuda_bf16.h>
#include <cstdint>

// Problem constants
#define BB   32
#define SS   64
#define DD   512
#define MM   8192
#define NHD  8
#define HD   64
#define NTOK (BB * SS)          // 2048
#define KSPLIT 4

typedef unsigned short u16;
typedef unsigned int   u32;

// ---------------------------------------------------------------------------
// Scratch (device globals per allocation rules)
// ---------------------------------------------------------------------------
__device__ float g_Q[NTOK * DD];           // Q projection output (fp32)
__device__ float g_KV[MM * 2 * DD];        // K|V projection output (fp32)
// Pre-split bf16 inputs/weights (hi/lo)
__device__ u16 g_qih[NTOK * DD],  g_qil[NTOK * DD];      // query input
__device__ u16 g_bkh[MM * DD],    g_bkl[MM * DD];        // memory_bank
__device__ u16 g_wih[3 * DD * DD], g_wil[3 * DD * DD];   // in_proj_w
__device__ u16 g_woh[DD * DD],    g_wol[DD * DD];        // out_proj_w
__device__ u16 g_aoh[NTOK * DD],  g_aol[NTOK * DD];      // attention output
// Attention operand layouts: K row-major [h][m][d], V transposed [h][d][m]
__device__ u16 g_Kh[NHD * MM * HD], g_Kl[NHD * MM * HD];
__device__ u16 g_Vth[NHD * HD * MM], g_Vtl[NHD * HD * MM];
// Split-K attention partials (unnormalized)
__device__ float g_Opart[KSPLIT][NTOK * DD];
__device__ float g_Lpart[KSPLIT][NTOK * NHD];

// ---------------------------------------------------------------------------
// Helpers
// ---------------------------------------------------------------------------
__device__ __forceinline__ u32 smem_u32(const void* p) {
    u32 a;
    asm("{ .reg .u64 t; cvta.to.shared.u64 t, %1; cvt.u32.u64 %0, t; }"
        : "=r"(a) : "l"(p));
    return a;
}
// Pack two fp32 into bf16x2 (lo half = a) and the bf16x2 of the residuals.
__device__ __forceinline__ void split2(float a, float b, u32& hi, u32& lo) {
    asm("cvt.rn.bf16x2.f32 %0, %1, %2;" : "=r"(hi) : "f"(b), "f"(a));
    float ra = a - __uint_as_float(hi << 16);
    float rb = b - __uint_as_float(hi & 0xffff0000u);
    asm("cvt.rn.bf16x2.f32 %0, %1, %2;" : "=r"(lo) : "f"(rb), "f"(ra));
}
__device__ __forceinline__ void split1(float x, u16& h, u16& l) {
    __nv_bfloat16 bh = __float2bfloat16(x);
    float r = x - __bfloat162float(bh);
    __nv_bfloat16 bl = __float2bfloat16(r);
    h = *(u16*)&bh;  l = *(u16*)&bl;
}
// m16n8k16 bf16 MMA, fp32 accumulate in place (not volatile -> schedulable).
__device__ __forceinline__ void mma16816(float* c, const u32* a, u32 b0, u32 b1) {
    asm("mma.sync.aligned.m16n8k16.row.col.f32.bf16.bf16.f32 "
        "{%0,%1,%2,%3}, {%4,%5,%6,%7}, {%8,%9}, {%0,%1,%2,%3};"
        : "+f"(c[0]), "+f"(c[1]), "+f"(c[2]), "+f"(c[3])
        : "r"(a[0]), "r"(a[1]), "r"(a[2]), "r"(a[3]), "r"(b0), "r"(b1));
}
// cp.async 16B (LDGSTS in SASS; base ISA)
__device__ __forceinline__ void cp16(u32 dst, const void* src) {
    asm volatile("cp.async.cg.shared.global [%0], [%1], 16;"
                 :: "r"(dst), "l"(src));
}
__device__ __forceinline__ void cp_commit() {
    asm volatile("cp.async.commit_group;");
}
template <int N>
__device__ __forceinline__ void cp_wait() {
    asm volatile("cp.async.wait_group %0;" :: "n"(N));
}

// ---------------------------------------------------------------------------
// Pre-split fp32 -> bf16 hi/lo. n multiple of 512; grid n/512, 256 threads.
// ---------------------------------------------------------------------------
__global__ __launch_bounds__(256) void split_f32(
    const float* __restrict__ src, u16* __restrict__ hi, u16* __restrict__ lo)
{
    int i = blockIdx.x * 256 + threadIdx.x;
    float2 v = *(const float2*)&src[2 * i];
    u32 h, l; split2(v.x, v.y, h, l);
    *(u32*)&hi[2 * i] = h;
    *(u32*)&lo[2 * i] = l;
}

// ---------------------------------------------------------------------------
// Tensor-core projection GEMM on pre-split operands:
//   C[MxN] = A[MxK]*W[NxK]^T + bias[N]   (3-pass bf16, fp32 MMA accumulate)
// Grid (N/64, M/128), 256 threads = 8 warps; warp w owns rows 16w..16w+15.
// cp.async double-buffered k-blocks of 64. LDS.32 fragment loads (R12 pattern).
// Dyn smem u16, per stage (stride 27648 u16 = 55296 B):
//   Ah[128][72] @0 | Al @9216 | Wh[64][72] @18432 | Wl @23040
// ---------------------------------------------------------------------------
#define GSTG   27648                    // u16 per stage
#define GPROJ_SMEM (2 * GSTG * 2)       // bytes = 110592

__device__ __forceinline__ void gemm_copy(
    u32 smb, int st, int k0, int tid,
    const u16* __restrict__ Ah_g, const u16* __restrict__ Al_g,
    const u16* __restrict__ Wh_g, const u16* __restrict__ Wl_g,
    int bm, int bn, int K)
{
    u32 base = smb + (u32)st * 55296;
    #pragma unroll
    for (int i = 0; i < 4; i++) {
        int idx = i * 256 + tid;
        int r = idx >> 3, c = idx & 7;
        u32 doff = (u32)(r * 144 + c * 16);
        size_t go = (size_t)(bm + r) * K + k0 + c * 8;
        cp16(base + doff,         Ah_g + go);
        cp16(base + 18432 + doff, Al_g + go);
    }
    #pragma unroll
    for (int i = 0; i < 2; i++) {
        int idx = i * 256 + tid;
        int r = idx >> 3, c = idx & 7;
        u32 doff = (u32)(r * 144 + c * 16);
        size_t go = (size_t)(bn + r) * K + k0 + c * 8;
        cp16(base + 36864 + doff, Wh_g + go);
        cp16(base + 46080 + doff, Wl_g + go);
    }
    cp_commit();
}

__global__ __launch_bounds__(256, 2) void gemm_mma(
    const u16* __restrict__ Ah_g, const u16* __restrict__ Al_g,
    const u16* __restrict__ Wh_g, const u16* __restrict__ Wl_g,
    const float* __restrict__ bias, float* __restrict__ C,
    int K, int N)
{
    extern __shared__ u16 sma[];
    const int tid = threadIdx.x, w = tid >> 5, lane = tid & 31;
    const int gid = lane >> 2, t4 = lane & 3;
    const int bm = blockIdx.y * 128, bn = blockIdx.x * 64;
    const u32 smb = smem_u32(sma);

    float acc[8][4];
    #pragma unroll
    for (int j = 0; j < 8; j++)
        #pragma unroll
        for (int i = 0; i < 4; i++) acc[j][i] = 0.f;

    const int nk = K / 64;
    gemm_copy(smb, 0, 0, tid, Ah_g, Al_g, Wh_g, Wl_g, bm, bn, K);

    for (int ki = 0; ki < nk; ki++) {
        const int st = ki & 1;
        if (ki + 1 < nk) {
            gemm_copy(smb, st ^ 1, (ki + 1) * 64, tid, Ah_g, Al_g, Wh_g, Wl_g,
                      bm, bn, K);
            cp_wait<1>();
        } else {
            cp_wait<0>();
        }
        __syncthreads();

        const int sb = st * GSTG;
        #pragma unroll
        for (int kk = 0; kk < 4; kk++) {
            int ar = sb + (16 * w + gid) * 72 + 16 * kk + 2 * t4;
            u32 ah[4], al[4];
            ah[0] = *(const u32*)&sma[ar];
            ah[1] = *(const u32*)&sma[ar + 8 * 72];
            ah[2] = *(const u32*)&sma[ar + 8];
            ah[3] = *(const u32*)&sma[ar + 8 * 72 + 8];
            al[0] = *(const u32*)&sma[ar + 9216];
            al[1] = *(const u32*)&sma[ar + 9216 + 8 * 72];
            al[2] = *(const u32*)&sma[ar + 9216 + 8];
            al[3] = *(const u32*)&sma[ar + 9216 + 8 * 72 + 8];
            #pragma unroll
            for (int j = 0; j < 8; j++) {
                int br = sb + 18432 + (8 * j + gid) * 72 + 16 * kk + 2 * t4;
                u32 bh0 = *(const u32*)&sma[br];
                u32 bh1 = *(const u32*)&sma[br + 8];
                u32 bl0 = *(const u32*)&sma[br + 4608];
                u32 bl1 = *(const u32*)&sma[br + 4608 + 8];
                mma16816(acc[j], ah, bh0, bh1);
                mma16816(acc[j], al, bh0, bh1);
                mma16816(acc[j], ah, bl0, bl1);
            }
        }
        __syncthreads();
    }

    #pragma unroll
    for (int j = 0; j < 8; j++) {
        int row = bm + 16 * w + gid;
        int col = bn + 8 * j + 2 * t4;
        float2 b2 = *(const float2*)&bias[col];
        *(float2*)&C[(size_t)row * N + col] =
            make_float2(acc[j][0] + b2.x, acc[j][1] + b2.y);
        *(float2*)&C[(size_t)(row + 8) * N + col] =
            make_float2(acc[j][2] + b2.x, acc[j][3] + b2.y);
    }
}

// ---------------------------------------------------------------------------
// Split K (row-major bf16 hi/lo) and V (transposed bf16 hi/lo).
// Grid (NHD, MM/64), 256 threads. V staged through smem for coalesced writes.
// ---------------------------------------------------------------------------
__global__ __launch_bounds__(256) void kv_split()
{
    __shared__ float vt[64][65];
    const int h = blockIdx.x, t = blockIdx.y;
    const int m0 = t * 64;
    const int tid = threadIdx.x;

    #pragma unroll
    for (int i = 0; i < 16; i++) {
        int idx = i * 256 + tid;
        int r = idx >> 6, d = idx & 63;
        size_t row = (size_t)(m0 + r) * (2 * DD);
        float kf = g_KV[row + h * HD + d];
        u16 kh, kl; split1(kf, kh, kl);
        size_t ko = ((size_t)h * MM + m0 + r) * HD + d;
        g_Kh[ko] = kh;  g_Kl[ko] = kl;
        vt[r][d] = g_KV[row + DD + h * HD + d];
    }
    __syncthreads();
    #pragma unroll
    for (int i = 0; i < 16; i++) {
        int idx = i * 256 + tid;
        int d = idx >> 6, r = idx & 63;
        u16 vh, vl; split1(vt[r][d], vh, vl);
        size_t vo = ((size_t)h * HD + d) * MM + m0 + r;
        g_Vth[vo] = vh;  g_Vtl[vo] = vl;
    }
}

// ---------------------------------------------------------------------------
// mma.sync flash attention, split-K, shift-free softmax.
// Grid (NHD, 16 q-blocks, KSPLIT), 256 threads = 8 warps.
// cp.async double-buffered 64-key tiles. LDS.32 fragment loads (R12 pattern).
// Dyn smem u16, per stage (stride 18432 u16 = 36864 B):
//   Kh[64][72] @0 | Kl @4608 | Vh @9216 | Vl @13824
// ---------------------------------------------------------------------------
#define ASTG 18432                      // u16 per stage
#define ATTN_SMEM (2 * ASTG * 2)        // bytes = 73728

__device__ __forceinline__ void attn_copy(
    u32 smb, int st, int t, int tid,
    const u16* __restrict__ Kh, const u16* __restrict__ Kl,
    const u16* __restrict__ Vth, const u16* __restrict__ Vtl)
{
    u32 base = smb + (u32)st * 36864;
    #pragma unroll
    for (int i = 0; i < 2; i++) {
        int idx = i * 256 + tid;
        int r = idx >> 3, c = idx & 7;
        u32 doff = (u32)(r * 144 + c * 16);
        cp16(base + doff,         Kh + (size_t)t * 4096 + idx * 8);
        cp16(base + 9216 + doff,  Kl + (size_t)t * 4096 + idx * 8);
        cp16(base + 18432 + doff, Vth + (size_t)r * MM + t * 64 + c * 8);
        cp16(base + 27648 + doff, Vtl + (size_t)r * MM + t * 64 + c * 8);
    }
    cp_commit();
}

__global__ __launch_bounds__(256, 2) void attn_mma()
{
    extern __shared__ u16 sma[];
    const int tid = threadIdx.x, w = tid >> 5, lane = tid & 31;
    const int h = blockIdx.x, bp = blockIdx.y, z = blockIdx.z;
    const int gid = lane >> 2, t4 = lane & 3;
    const int q0 = bp * 128 + w * 16;
    const u32 smb = smem_u32(sma);

    const u16* Khp  = g_Kh  + ((size_t)h * MM) * HD;
    const u16* Klp  = g_Kl  + ((size_t)h * MM) * HD;
    const u16* Vthp = g_Vth + ((size_t)h * HD) * MM;
    const u16* Vtlp = g_Vtl + ((size_t)h * HD) * MM;

    // --- Q fragments (fp32 load, scale 1/8, split to hi/lo bf16x2) ---
    u32 qh[4][4], ql[4][4];
    #pragma unroll
    for (int kk = 0; kk < 4; kk++) {
        const float* qb = &g_Q[(size_t)(q0 + gid) * DD + h * HD + 16 * kk + 2 * t4];
        float2 v;
        v = *(const float2*)(qb);
        split2(v.x * 0.125f, v.y * 0.125f, qh[kk][0], ql[kk][0]);
        v = *(const float2*)(qb + 8 * DD);
        split2(v.x * 0.125f, v.y * 0.125f, qh[kk][1], ql[kk][1]);
        v = *(const float2*)(qb + 8);
        split2(v.x * 0.125f, v.y * 0.125f, qh[kk][2], ql[kk][2]);
        v = *(const float2*)(qb + 8 * DD + 8);
        split2(v.x * 0.125f, v.y * 0.125f, qh[kk][3], ql[kk][3]);
    }

    float oacc[8][4];
    #pragma unroll
    for (int j = 0; j < 8; j++)
        #pragma unroll
        for (int i = 0; i < 4; i++) oacc[j][i] = 0.f;
    float ls0 = 0.f, ls1 = 0.f;

    const int t0 = z * (MM / 64 / KSPLIT);
    const int t1 = t0 + MM / 64 / KSPLIT;

    attn_copy(smb, 0, t0, tid, Khp, Klp, Vthp, Vtlp);

    for (int t = t0; t < t1; t++) {
        const int st = t & 1;
        if (t + 1 < t1) {
            attn_copy(smb, st ^ 1, t + 1, tid, Khp, Klp, Vthp, Vtlp);
            cp_wait<1>();
        } else {
            cp_wait<0>();
        }
        __syncthreads();

        const int sb = st * ASTG;

        // --- S = Q K^T ---
        float sacc[8][4];
        #pragma unroll
        for (int j = 0; j < 8; j++)
            #pragma unroll
            for (int i = 0; i < 4; i++) sacc[j][i] = 0.f;

        #pragma unroll
        for (int kk = 0; kk < 4; kk++) {
            #pragma unroll
            for (int j = 0; j < 8; j++) {
                int br = sb + (8 * j + gid) * 72 + 16 * kk + 2 * t4;
                u32 bh0 = *(const u32*)&sma[br];
                u32 bh1 = *(const u32*)&sma[br + 8];
                u32 bl0 = *(const u32*)&sma[br + 4608];
                u32 bl1 = *(const u32*)&sma[br + 4608 + 8];
                mma16816(sacc[j], qh[kk], bh0, bh1);
                mma16816(sacc[j], ql[kk], bh0, bh1);
                mma16816(sacc[j], qh[kk], bl0, bl1);
            }
        }

        // --- exp, row-sum, P fragments (hi/lo) ---
        u32 ph[4][4], pl[4][4];
        #pragma unroll
        for (int j = 0; j < 8; j++) {
            float e0 = __expf(sacc[j][0]);
            float e1 = __expf(sacc[j][1]);
            float e2 = __expf(sacc[j][2]);
            float e3 = __expf(sacc[j][3]);
            ls0 += e0 + e1;
            ls1 += e2 + e3;
            int kk = j >> 1, sl = (j & 1) * 2;
            split2(e0, e1, ph[kk][sl + 0], pl[kk][sl + 0]);
            split2(e2, e3, ph[kk][sl + 1], pl[kk][sl + 1]);
        }

        // --- O += P V ---
        #pragma unroll
        for (int kk = 0; kk < 4; kk++) {
            #pragma unroll
            for (int j = 0; j < 8; j++) {
                int br = sb + 9216 + (8 * j + gid) * 72 + 16 * kk + 2 * t4;
                u32 bh0 = *(const u32*)&sma[br];
                u32 bh1 = *(const u32*)&sma[br + 8];
                u32 bl0 = *(const u32*)&sma[br + 4608];
                u32 bl1 = *(const u32*)&sma[br + 4608 + 8];
                mma16816(oacc[j], ph[kk], bh0, bh1);
                mma16816(oacc[j], pl[kk], bh0, bh1);
                mma16816(oacc[j], ph[kk], bl0, bl1);
            }
        }
        __syncthreads();     // all warps done with stage st before it is refilled
    }

    // --- finalize: quad-reduce row sums, write unnormalized partials ---
    ls0 += __shfl_xor_sync(0xffffffffu, ls0, 1);
    ls0 += __shfl_xor_sync(0xffffffffu, ls0, 2);
    ls1 += __shfl_xor_sync(0xffffffffu, ls1, 1);
    ls1 += __shfl_xor_sync(0xffffffffu, ls1, 2);
    if (t4 == 0) {
        g_Lpart[z][(q0 + gid) * NHD + h]     = ls0;
        g_Lpart[z][(q0 + gid + 8) * NHD + h] = ls1;
    }
    #pragma unroll
    for (int j = 0; j < 8; j++) {
        float* d0 = &g_Opart[z][(size_t)(q0 + gid) * DD + h * HD + 8 * j + 2 * t4];
        *(float2*)d0 = make_float2(oacc[j][0], oacc[j][1]);
        float* d1 = d0 + 8 * DD;
        *(float2*)d1 = make_float2(oacc[j][2], oacc[j][3]);
    }
}

// ---------------------------------------------------------------------------
// Split-K reduce: AO = (sum_z Opart) / (sum_z Lpart), written pre-split bf16.
// Grid NTOK, 256 threads (2 adjacent elements each).
// ---------------------------------------------------------------------------
__global__ __launch_bounds__(256) void attn_reduce()
{
    const int q = blockIdx.x;
    const int d0 = threadIdx.x * 2;
    const int h = d0 >> 6;
    float l = 0.f, o0 = 0.f, o1 = 0.f;
    #pragma unroll
    for (int s = 0; s < KSPLIT; s++) {
        l += g_Lpart[s][q * NHD + h];
        float2 v = *(const float2*)&g_Opart[s][(size_t)q * DD + d0];
        o0 += v.x;  o1 += v.y;
    }
    float inv = 1.f / l;
    u32 hh, ll;
    split2(o0 * inv, o1 * inv, hh, ll);
    *(u32*)&g_aoh[(size_t)q * DD + d0] = hh;
    *(u32*)&g_aol[(size_t)q * DD + d0] = ll;
}

// ---------------------------------------------------------------------------
// Bank update
// ---------------------------------------------------------------------------
__global__ __launch_bounds__(128) void bank_update(
    const float* __restrict__ memory, const float* __restrict__ bank,
    const int* __restrict__ ptrp, float* __restrict__ outbank)
{
    int r = blockIdx.x;
    int ptr = ptrp[0];
    int rel = (r - ptr) % MM;
    if (rel < 0) rel += MM;
    const float* src = (rel < NTOK) ? (memory + (size_t)rel * DD)
                                    : (bank + (size_t)r * DD);
    float4 v = *(const float4*)(src + threadIdx.x * 4);
    *(float4*)(outbank + (size_t)r * DD + threadIdx.x * 4) = v;
}

// ---------------------------------------------------------------------------
// Launch
// ---------------------------------------------------------------------------
extern "C" void kernel_launch(void* const* d_in, const int* in_sizes, int n_in,
                              void* d_out, int out_size)
{
    const float* query  = (const float*)d_in[0];
    const float* memory = (const float*)d_in[1];
    const float* bank   = (const float*)d_in[2];
    const float* ipw    = (const float*)d_in[3];
    const float* ipb    = (const float*)d_in[4];
    const float* opw    = (const float*)d_in[5];
    const float* opb    = (const float*)d_in[6];
    const int*   ptr    = (const int*)d_in[7];
    float* out = (float*)d_out;

    float *pQ, *pKV;
    cudaGetSymbolAddress((void**)&pQ, g_Q);
    cudaGetSymbolAddress((void**)&pKV, g_KV);
    u16 *pqih, *pqil, *pbkh, *pbkl, *pwih, *pwil, *pwoh, *pwol, *paoh, *paol;
    cudaGetSymbolAddress((void**)&pqih, g_qih);
    cudaGetSymbolAddress((void**)&pqil, g_qil);
    cudaGetSymbolAddress((void**)&pbkh, g_bkh);
    cudaGetSymbolAddress((void**)&pbkl, g_bkl);
    cudaGetSymbolAddress((void**)&pwih, g_wih);
    cudaGetSymbolAddress((void**)&pwil, g_wil);
    cudaGetSymbolAddress((void**)&pwoh, g_woh);
    cudaGetSymbolAddress((void**)&pwol, g_wol);
    cudaGetSymbolAddress((void**)&paoh, g_aoh);
    cudaGetSymbolAddress((void**)&paol, g_aol);

    cudaFuncSetAttribute(gemm_mma, cudaFuncAttributeMaxDynamicSharedMemorySize,
                         GPROJ_SMEM);
    cudaFuncSetAttribute(attn_mma, cudaFuncAttributeMaxDynamicSharedMemorySize,
                         ATTN_SMEM);

    // 0) pre-split inputs and weights to bf16 hi/lo
    split_f32<<<NTOK * DD / 512, 256>>>(query, pqih, pqil);
    split_f32<<<MM * DD / 512, 256>>>(bank, pbkh, pbkl);
    split_f32<<<3 * DD * DD / 512, 256>>>(ipw, pwih, pwil);
    split_f32<<<DD * DD / 512, 256>>>(opw, pwoh, pwol);

    // 1) Q = query @ Wq^T + bq            [2048 x 512]
    gemm_mma<<<dim3(DD / 64, NTOK / 128), 256, GPROJ_SMEM>>>(
        pqih, pqil, pwih, pwil, ipb, pQ, DD, DD);
    // 2) K|V = bank @ [Wk;Wv]^T + [bk;bv] [8192 x 1024]
    gemm_mma<<<dim3(2 * DD / 64, MM / 128), 256, GPROJ_SMEM>>>(
        pbkh, pbkl, pwih + (size_t)DD * DD, pwil + (size_t)DD * DD,
        ipb + DD, pKV, DD, 2 * DD);
    // 3) split K / transpose+split V to attention layouts
    kv_split<<<dim3(NHD, MM / 64), 256>>>();
    // 4) split-K mma.sync flash attention -> partials
    attn_mma<<<dim3(NHD, 16, KSPLIT), 256, ATTN_SMEM>>>();
    // 5) combine partials -> pre-split AO
    attn_reduce<<<NTOK, 256>>>();
    // 6) retrieved = AO @ out_proj^T + b
    gemm_mma<<<dim3(DD / 64, NTOK / 128), 256, GPROJ_SMEM>>>(
        paoh, paol, pwoh, pwol, opb, out, DD, DD);
    // 7) new bank
    bank_update<<<MM, 128>>>(memory, bank, ptr, out + (size_t)NTOK * DD);
}

// round 17
// speedup vs baseline: 1.6142x; 1.0405x over previous
#include <cuda_runtime.h>
#include <cuda_bf16.h>
#include <cstdint>

// Problem constants
#define BB   32
#define SS   64
#define DD   512
#define MM   8192
#define NHD  8
#define HD   64
#define NTOK (BB * SS)          // 2048
#define KSPLIT 4

typedef unsigned short u16;
typedef unsigned int   u32;

// ---------------------------------------------------------------------------
// Scratch (device globals per allocation rules)
// ---------------------------------------------------------------------------
__device__ float g_Q[NTOK * DD];           // Q projection output (fp32)
__device__ float g_KV[MM * 2 * DD];        // K|V projection output (fp32)
// Pre-split bf16 inputs/weights (hi/lo) for projection GEMMs
__device__ u16 g_qih[NTOK * DD],  g_qil[NTOK * DD];      // query input
__device__ u16 g_bkh[MM * DD],    g_bkl[MM * DD];        // memory_bank
__device__ u16 g_wih[3 * DD * DD], g_wil[3 * DD * DD];   // in_proj_w
__device__ u16 g_woh[DD * DD],    g_wol[DD * DD];        // out_proj_w
__device__ u16 g_aoh[NTOK * DD],  g_aol[NTOK * DD];      // attention output
// Attention operands, fragment-interleaved:
// per row (64 per tile): 16 units of 8 u16 = [bh0,bh1,bl0,bl1] for (kk,t4).
// K rows = keys (m). V rows = dims (d), k-dim = keys within tile.
__device__ u16 g_KI[NHD * MM * 128];
__device__ u16 g_VI[NHD * MM * 128];
// Split-K attention partials (unnormalized)
__device__ float g_Opart[KSPLIT][NTOK * DD];
__device__ float g_Lpart[KSPLIT][NTOK * NHD];

// ---------------------------------------------------------------------------
// Helpers
// ---------------------------------------------------------------------------
__device__ __forceinline__ u32 smem_u32(const void* p) {
    u32 a;
    asm("{ .reg .u64 t; cvta.to.shared.u64 t, %1; cvt.u32.u64 %0, t; }"
        : "=r"(a) : "l"(p));
    return a;
}
// Pack two fp32 into bf16x2 (lo half = a) and the bf16x2 of the residuals.
__device__ __forceinline__ void split2(float a, float b, u32& hi, u32& lo) {
    asm("cvt.rn.bf16x2.f32 %0, %1, %2;" : "=r"(hi) : "f"(b), "f"(a));
    float ra = a - __uint_as_float(hi << 16);
    float rb = b - __uint_as_float(hi & 0xffff0000u);
    asm("cvt.rn.bf16x2.f32 %0, %1, %2;" : "=r"(lo) : "f"(rb), "f"(ra));
}
__device__ __forceinline__ void split1(float x, u16& h, u16& l) {
    __nv_bfloat16 bh = __float2bfloat16(x);
    float r = x - __bfloat162float(bh);
    __nv_bfloat16 bl = __float2bfloat16(r);
    h = *(u16*)&bh;  l = *(u16*)&bl;
}
// m16n8k16 bf16 MMA, fp32 accumulate in place (not volatile -> schedulable).
__device__ __forceinline__ void mma16816(float* c, const u32* a, u32 b0, u32 b1) {
    asm("mma.sync.aligned.m16n8k16.row.col.f32.bf16.bf16.f32 "
        "{%0,%1,%2,%3}, {%4,%5,%6,%7}, {%8,%9}, {%0,%1,%2,%3};"
        : "+f"(c[0]), "+f"(c[1]), "+f"(c[2]), "+f"(c[3])
        : "r"(a[0]), "r"(a[1]), "r"(a[2]), "r"(a[3]), "r"(b0), "r"(b1));
}
// cp.async 16B (LDGSTS in SASS; base ISA)
__device__ __forceinline__ void cp16(u32 dst, const void* src) {
    asm volatile("cp.async.cg.shared.global [%0], [%1], 16;"
                 :: "r"(dst), "l"(src));
}
__device__ __forceinline__ void cp_commit() {
    asm volatile("cp.async.commit_group;");
}
template <int N>
__device__ __forceinline__ void cp_wait() {
    asm volatile("cp.async.wait_group %0;" :: "n"(N));
}

// ---------------------------------------------------------------------------
// Pre-split fp32 -> bf16 hi/lo. n multiple of 512; grid n/512, 256 threads.
// ---------------------------------------------------------------------------
__global__ __launch_bounds__(256) void split_f32(
    const float* __restrict__ src, u16* __restrict__ hi, u16* __restrict__ lo)
{
    int i = blockIdx.x * 256 + threadIdx.x;
    float2 v = *(const float2*)&src[2 * i];
    u32 h, l; split2(v.x, v.y, h, l);
    *(u32*)&hi[2 * i] = h;
    *(u32*)&lo[2 * i] = l;
}

// ---------------------------------------------------------------------------
// Tensor-core projection GEMM on pre-split operands (UNCHANGED from R16):
//   C[MxN] = A[MxK]*W[NxK]^T + bias[N]   (3-pass bf16, fp32 MMA accumulate)
// ---------------------------------------------------------------------------
#define GSTG   27648                    // u16 per stage
#define GPROJ_SMEM (2 * GSTG * 2)       // bytes = 110592

__device__ __forceinline__ void gemm_copy(
    u32 smb, int st, int k0, int tid,
    const u16* __restrict__ Ah_g, const u16* __restrict__ Al_g,
    const u16* __restrict__ Wh_g, const u16* __restrict__ Wl_g,
    int bm, int bn, int K)
{
    u32 base = smb + (u32)st * 55296;
    #pragma unroll
    for (int i = 0; i < 4; i++) {
        int idx = i * 256 + tid;
        int r = idx >> 3, c = idx & 7;
        u32 doff = (u32)(r * 144 + c * 16);
        size_t go = (size_t)(bm + r) * K + k0 + c * 8;
        cp16(base + doff,         Ah_g + go);
        cp16(base + 18432 + doff, Al_g + go);
    }
    #pragma unroll
    for (int i = 0; i < 2; i++) {
        int idx = i * 256 + tid;
        int r = idx >> 3, c = idx & 7;
        u32 doff = (u32)(r * 144 + c * 16);
        size_t go = (size_t)(bn + r) * K + k0 + c * 8;
        cp16(base + 36864 + doff, Wh_g + go);
        cp16(base + 46080 + doff, Wl_g + go);
    }
    cp_commit();
}

__global__ __launch_bounds__(256, 2) void gemm_mma(
    const u16* __restrict__ Ah_g, const u16* __restrict__ Al_g,
    const u16* __restrict__ Wh_g, const u16* __restrict__ Wl_g,
    const float* __restrict__ bias, float* __restrict__ C,
    int K, int N)
{
    extern __shared__ u16 sma[];
    const int tid = threadIdx.x, w = tid >> 5, lane = tid & 31;
    const int gid = lane >> 2, t4 = lane & 3;
    const int bm = blockIdx.y * 128, bn = blockIdx.x * 64;
    const u32 smb = smem_u32(sma);

    float acc[8][4];
    #pragma unroll
    for (int j = 0; j < 8; j++)
        #pragma unroll
        for (int i = 0; i < 4; i++) acc[j][i] = 0.f;

    const int nk = K / 64;
    gemm_copy(smb, 0, 0, tid, Ah_g, Al_g, Wh_g, Wl_g, bm, bn, K);

    for (int ki = 0; ki < nk; ki++) {
        const int st = ki & 1;
        if (ki + 1 < nk) {
            gemm_copy(smb, st ^ 1, (ki + 1) * 64, tid, Ah_g, Al_g, Wh_g, Wl_g,
                      bm, bn, K);
            cp_wait<1>();
        } else {
            cp_wait<0>();
        }
        __syncthreads();

        const int sb = st * GSTG;
        #pragma unroll
        for (int kk = 0; kk < 4; kk++) {
            int ar = sb + (16 * w + gid) * 72 + 16 * kk + 2 * t4;
            u32 ah[4], al[4];
            ah[0] = *(const u32*)&sma[ar];
            ah[1] = *(const u32*)&sma[ar + 8 * 72];
            ah[2] = *(const u32*)&sma[ar + 8];
            ah[3] = *(const u32*)&sma[ar + 8 * 72 + 8];
            al[0] = *(const u32*)&sma[ar + 9216];
            al[1] = *(const u32*)&sma[ar + 9216 + 8 * 72];
            al[2] = *(const u32*)&sma[ar + 9216 + 8];
            al[3] = *(const u32*)&sma[ar + 9216 + 8 * 72 + 8];
            #pragma unroll
            for (int j = 0; j < 8; j++) {
                int br = sb + 18432 + (8 * j + gid) * 72 + 16 * kk + 2 * t4;
                u32 bh0 = *(const u32*)&sma[br];
                u32 bh1 = *(const u32*)&sma[br + 8];
                u32 bl0 = *(const u32*)&sma[br + 4608];
                u32 bl1 = *(const u32*)&sma[br + 4608 + 8];
                mma16816(acc[j], ah, bh0, bh1);
                mma16816(acc[j], al, bh0, bh1);
                mma16816(acc[j], ah, bl0, bl1);
            }
        }
        __syncthreads();
    }

    #pragma unroll
    for (int j = 0; j < 8; j++) {
        int row = bm + 16 * w + gid;
        int col = bn + 8 * j + 2 * t4;
        float2 b2 = *(const float2*)&bias[col];
        *(float2*)&C[(size_t)row * N + col] =
            make_float2(acc[j][0] + b2.x, acc[j][1] + b2.y);
        *(float2*)&C[(size_t)(row + 8) * N + col] =
            make_float2(acc[j][2] + b2.x, acc[j][3] + b2.y);
    }
}

// ---------------------------------------------------------------------------
// Split K and V into the fragment-interleaved attention layout.
// Grid (NHD, MM/64), 256 threads.
// Unit for (row, kk, t4) = 8 u16: [hi(16kk+2t4), hi(+1), hi(16kk+2t4+8),
// hi(+9), lo(...x4)]. K rows = keys; V rows = dims (transposed, staged via
// smem so global writes stay row-contiguous).
// ---------------------------------------------------------------------------
__global__ __launch_bounds__(256) void kv_split()
{
    __shared__ float vt[64][65];
    const int h = blockIdx.x, t = blockIdx.y;
    const int m0 = t * 64;
    const int tid = threadIdx.x;

    #pragma unroll
    for (int i = 0; i < 16; i++) {
        int idx = i * 256 + tid;
        int r = idx >> 6, d = idx & 63;
        size_t row = (size_t)(m0 + r) * (2 * DD);
        // K element (key m0+r, dim d) -> interleaved unit in row (m0+r)
        float kf = g_KV[row + h * HD + d];
        u16 kh, kl; split1(kf, kh, kl);
        int p8 = d & 15;
        int sl = ((p8 >> 3) << 1) | (d & 1);
        int un = (d >> 4) * 4 + ((p8 & 7) >> 1);
        size_t kb = ((size_t)h * MM + m0 + r) * 128 + un * 8;
        g_KI[kb + sl]     = kh;
        g_KI[kb + 4 + sl] = kl;
        // stage V for transpose
        vt[r][d] = g_KV[row + DD + h * HD + d];
    }
    __syncthreads();
    #pragma unroll
    for (int i = 0; i < 16; i++) {
        int idx = i * 256 + tid;
        int d = idx >> 6, r = idx & 63;    // V row = dim d, k-col = key r
        u16 vh, vl; split1(vt[r][d], vh, vl);
        int q8 = r & 15;
        int sl = ((q8 >> 3) << 1) | (r & 1);
        int un = (r >> 4) * 4 + ((q8 & 7) >> 1);
        size_t vb = ((size_t)h * MM + m0 + d) * 128 + un * 8;
        g_VI[vb + sl]     = vh;
        g_VI[vb + 4 + sl] = vl;
    }
}

// ---------------------------------------------------------------------------
// mma.sync flash attention, split-K, shift-free softmax.
// Grid (NHD, 16 q-blocks, KSPLIT), 256 threads = 8 warps.
// cp.async double-buffered tiles. B-fragments: ONE LDS.128 per (j,kk) yields
// bh0,bh1,bl0,bl1 (interleaved layout, row stride 320B -> conflict-free).
// Dyn smem per stage 40960B: K tile @0 (64 rows x 320B), V tile @20480.
// ---------------------------------------------------------------------------
#define ASTGB 40960
#define ATTN_SMEM (2 * ASTGB)            // 81920 bytes

__device__ __forceinline__ void attn_copy(
    u32 smb, int st, int t, int tid,
    const u16* __restrict__ Ksrc, const u16* __restrict__ Vsrc)
{
    u32 base = smb + (u32)st * ASTGB;
    #pragma unroll
    for (int i = 0; i < 4; i++) {
        int idx = i * 256 + tid;              // 0..1023 units of 16B
        int r = idx >> 4, u = idx & 15;
        u32 doff = (u32)(r * 320 + u * 16);
        cp16(base + doff,         Ksrc + (size_t)t * 8192 + idx * 8);
        cp16(base + 20480 + doff, Vsrc + (size_t)t * 8192 + idx * 8);
    }
    cp_commit();
}

__global__ __launch_bounds__(256, 2) void attn_mma()
{
    extern __shared__ u16 sma[];
    const int tid = threadIdx.x, w = tid >> 5, lane = tid & 31;
    const int h = blockIdx.x, bp = blockIdx.y, z = blockIdx.z;
    const int gid = lane >> 2, t4 = lane & 3;
    const int q0 = bp * 128 + w * 16;
    const u32 smb = smem_u32(sma);
    const char* smc = (const char*)sma;

    const u16* Ksrc = g_KI + ((size_t)h * MM) * 128;
    const u16* Vsrc = g_VI + ((size_t)h * MM) * 128;

    // --- Q fragments (fp32 load, scale 1/8, split to hi/lo bf16x2) ---
    u32 qh[4][4], ql[4][4];
    #pragma unroll
    for (int kk = 0; kk < 4; kk++) {
        const float* qb = &g_Q[(size_t)(q0 + gid) * DD + h * HD + 16 * kk + 2 * t4];
        float2 v;
        v = *(const float2*)(qb);
        split2(v.x * 0.125f, v.y * 0.125f, qh[kk][0], ql[kk][0]);
        v = *(const float2*)(qb + 8 * DD);
        split2(v.x * 0.125f, v.y * 0.125f, qh[kk][1], ql[kk][1]);
        v = *(const float2*)(qb + 8);
        split2(v.x * 0.125f, v.y * 0.125f, qh[kk][2], ql[kk][2]);
        v = *(const float2*)(qb + 8 * DD + 8);
        split2(v.x * 0.125f, v.y * 0.125f, qh[kk][3], ql[kk][3]);
    }

    float oacc[8][4];
    #pragma unroll
    for (int j = 0; j < 8; j++)
        #pragma unroll
        for (int i = 0; i < 4; i++) oacc[j][i] = 0.f;
    float ls0 = 0.f, ls1 = 0.f;

    const int t0 = z * (MM / 64 / KSPLIT);
    const int t1 = t0 + MM / 64 / KSPLIT;

    attn_copy(smb, 0, t0, tid, Ksrc, Vsrc);

    for (int t = t0; t < t1; t++) {
        const int st = t & 1;
        if (t + 1 < t1) {
            attn_copy(smb, st ^ 1, t + 1, tid, Ksrc, Vsrc);
            cp_wait<1>();
        } else {
            cp_wait<0>();
        }
        __syncthreads();

        // Per-thread fragment base pointers for this stage
        const char* kp = smc + st * ASTGB + gid * 320 + t4 * 16;
        const char* vp = kp + 20480;

        // --- S = Q K^T ---
        float sacc[8][4];
        #pragma unroll
        for (int j = 0; j < 8; j++)
            #pragma unroll
            for (int i = 0; i < 4; i++) sacc[j][i] = 0.f;

        #pragma unroll
        for (int kk = 0; kk < 4; kk++) {
            #pragma unroll
            for (int j = 0; j < 8; j++) {
                uint4 b = *(const uint4*)(kp + j * 2560 + kk * 64);
                mma16816(sacc[j], qh[kk], b.x, b.y);
                mma16816(sacc[j], ql[kk], b.x, b.y);
                mma16816(sacc[j], qh[kk], b.z, b.w);
            }
        }

        // --- exp, row-sum, P fragments (hi/lo) ---
        u32 ph[4][4], pl[4][4];
        #pragma unroll
        for (int j = 0; j < 8; j++) {
            float e0 = __expf(sacc[j][0]);
            float e1 = __expf(sacc[j][1]);
            float e2 = __expf(sacc[j][2]);
            float e3 = __expf(sacc[j][3]);
            ls0 += e0 + e1;
            ls1 += e2 + e3;
            int kk = j >> 1, sl = (j & 1) * 2;
            split2(e0, e1, ph[kk][sl + 0], pl[kk][sl + 0]);
            split2(e2, e3, ph[kk][sl + 1], pl[kk][sl + 1]);
        }

        // --- O += P V ---
        #pragma unroll
        for (int kk = 0; kk < 4; kk++) {
            #pragma unroll
            for (int j = 0; j < 8; j++) {
                uint4 b = *(const uint4*)(vp + j * 2560 + kk * 64);
                mma16816(oacc[j], ph[kk], b.x, b.y);
                mma16816(oacc[j], pl[kk], b.x, b.y);
                mma16816(oacc[j], ph[kk], b.z, b.w);
            }
        }
        __syncthreads();     // all warps done with stage st before refill
    }

    // --- finalize: quad-reduce row sums, write unnormalized partials ---
    ls0 += __shfl_xor_sync(0xffffffffu, ls0, 1);
    ls0 += __shfl_xor_sync(0xffffffffu, ls0, 2);
    ls1 += __shfl_xor_sync(0xffffffffu, ls1, 1);
    ls1 += __shfl_xor_sync(0xffffffffu, ls1, 2);
    if (t4 == 0) {
        g_Lpart[z][(q0 + gid) * NHD + h]     = ls0;
        g_Lpart[z][(q0 + gid + 8) * NHD + h] = ls1;
    }
    #pragma unroll
    for (int j = 0; j < 8; j++) {
        float* d0 = &g_Opart[z][(size_t)(q0 + gid) * DD + h * HD + 8 * j + 2 * t4];
        *(float2*)d0 = make_float2(oacc[j][0], oacc[j][1]);
        float* d1 = d0 + 8 * DD;
        *(float2*)d1 = make_float2(oacc[j][2], oacc[j][3]);
    }
}

// ---------------------------------------------------------------------------
// Split-K reduce: AO = (sum_z Opart) / (sum_z Lpart), written pre-split bf16.
// ---------------------------------------------------------------------------
__global__ __launch_bounds__(256) void attn_reduce()
{
    const int q = blockIdx.x;
    const int d0 = threadIdx.x * 2;
    const int h = d0 >> 6;
    float l = 0.f, o0 = 0.f, o1 = 0.f;
    #pragma unroll
    for (int s = 0; s < KSPLIT; s++) {
        l += g_Lpart[s][q * NHD + h];
        float2 v = *(const float2*)&g_Opart[s][(size_t)q * DD + d0];
        o0 += v.x;  o1 += v.y;
    }
    float inv = 1.f / l;
    u32 hh, ll;
    split2(o0 * inv, o1 * inv, hh, ll);
    *(u32*)&g_aoh[(size_t)q * DD + d0] = hh;
    *(u32*)&g_aol[(size_t)q * DD + d0] = ll;
}

// ---------------------------------------------------------------------------
// Bank update
// ---------------------------------------------------------------------------
__global__ __launch_bounds__(128) void bank_update(
    const float* __restrict__ memory, const float* __restrict__ bank,
    const int* __restrict__ ptrp, float* __restrict__ outbank)
{
    int r = blockIdx.x;
    int ptr = ptrp[0];
    int rel = (r - ptr) % MM;
    if (rel < 0) rel += MM;
    const float* src = (rel < NTOK) ? (memory + (size_t)rel * DD)
                                    : (bank + (size_t)r * DD);
    float4 v = *(const float4*)(src + threadIdx.x * 4);
    *(float4*)(outbank + (size_t)r * DD + threadIdx.x * 4) = v;
}

// ---------------------------------------------------------------------------
// Launch
// ---------------------------------------------------------------------------
extern "C" void kernel_launch(void* const* d_in, const int* in_sizes, int n_in,
                              void* d_out, int out_size)
{
    const float* query  = (const float*)d_in[0];
    const float* memory = (const float*)d_in[1];
    const float* bank   = (const float*)d_in[2];
    const float* ipw    = (const float*)d_in[3];
    const float* ipb    = (const float*)d_in[4];
    const float* opw    = (const float*)d_in[5];
    const float* opb    = (const float*)d_in[6];
    const int*   ptr    = (const int*)d_in[7];
    float* out = (float*)d_out;

    float *pQ, *pKV;
    cudaGetSymbolAddress((void**)&pQ, g_Q);
    cudaGetSymbolAddress((void**)&pKV, g_KV);
    u16 *pqih, *pqil, *pbkh, *pbkl, *pwih, *pwil, *pwoh, *pwol, *paoh, *paol;
    cudaGetSymbolAddress((void**)&pqih, g_qih);
    cudaGetSymbolAddress((void**)&pqil, g_qil);
    cudaGetSymbolAddress((void**)&pbkh, g_bkh);
    cudaGetSymbolAddress((void**)&pbkl, g_bkl);
    cudaGetSymbolAddress((void**)&pwih, g_wih);
    cudaGetSymbolAddress((void**)&pwil, g_wil);
    cudaGetSymbolAddress((void**)&pwoh, g_woh);
    cudaGetSymbolAddress((void**)&pwol, g_wol);
    cudaGetSymbolAddress((void**)&paoh, g_aoh);
    cudaGetSymbolAddress((void**)&paol, g_aol);

    cudaFuncSetAttribute(gemm_mma, cudaFuncAttributeMaxDynamicSharedMemorySize,
                         GPROJ_SMEM);
    cudaFuncSetAttribute(attn_mma, cudaFuncAttributeMaxDynamicSharedMemorySize,
                         ATTN_SMEM);

    // 0) pre-split inputs and weights to bf16 hi/lo
    split_f32<<<NTOK * DD / 512, 256>>>(query, pqih, pqil);
    split_f32<<<MM * DD / 512, 256>>>(bank, pbkh, pbkl);
    split_f32<<<3 * DD * DD / 512, 256>>>(ipw, pwih, pwil);
    split_f32<<<DD * DD / 512, 256>>>(opw, pwoh, pwol);

    // 1) Q = query @ Wq^T + bq            [2048 x 512]
    gemm_mma<<<dim3(DD / 64, NTOK / 128), 256, GPROJ_SMEM>>>(
        pqih, pqil, pwih, pwil, ipb, pQ, DD, DD);
    // 2) K|V = bank @ [Wk;Wv]^T + [bk;bv] [8192 x 1024]
    gemm_mma<<<dim3(2 * DD / 64, MM / 128), 256, GPROJ_SMEM>>>(
        pbkh, pbkl, pwih + (size_t)DD * DD, pwil + (size_t)DD * DD,
        ipb + DD, pKV, DD, 2 * DD);
    // 3) split K / transpose+split V into fragment-interleaved layout
    kv_split<<<dim3(NHD, MM / 64), 256>>>();
    // 4) split-K mma.sync flash attention -> partials
    attn_mma<<<dim3(NHD, 16, KSPLIT), 256, ATTN_SMEM>>>();
    // 5) combine partials -> pre-split AO
    attn_reduce<<<NTOK, 256>>>();
    // 6) retrieved = AO @ out_proj^T + b
    gemm_mma<<<dim3(DD / 64, NTOK / 128), 256, GPROJ_SMEM>>>(
        paoh, paol, pwoh, pwol, opb, out, DD, DD);
    // 7) new bank
    bank_update<<<MM, 128>>>(memory, bank, ptr, out + (size_t)NTOK * DD);
}